// round 1
// baseline (speedup 1.0000x reference)
#include <cuda_runtime.h>
#include <math.h>
#include <stdint.h>

#define NT 8192
#define TK 2
#define NE 8
#define DM 1024
#define DF 2048
#define CAP 3072

// ---- scratch (device globals; no runtime allocation allowed) ----
__device__ int   g_cnt[NE];
__device__ int   g_tok[NE * CAP];
__device__ float g_wt[NE * CAP];
__device__ float g_hidden[(size_t)NE * CAP * DF];   // 201 MB

// ---------------- dispatch ----------------
__global__ void k_zero() {
    if (threadIdx.x < NE) g_cnt[threadIdx.x] = 0;
}

__global__ void k_dispatch(const int* __restrict__ idx, const float* __restrict__ w) {
    int i = blockIdx.x * blockDim.x + threadIdx.x;
    if (i >= NT * TK) return;
    int e = idx[i];
    int p = atomicAdd(&g_cnt[e], 1);
    if (p < CAP) {
        g_tok[e * CAP + p] = i >> 1;   // token id
        g_wt[e * CAP + p]  = w[i];
    }
}

// ---------------- packed f32x2 helpers ----------------
__device__ __forceinline__ uint64_t pack2(float v) {
    uint64_t r; asm("mov.b64 %0, {%1, %1};" : "=l"(r) : "f"(v)); return r;
}
__device__ __forceinline__ uint64_t fma2(uint64_t a, uint64_t b, uint64_t c) {
    uint64_t d; asm("fma.rn.f32x2 %0, %1, %2, %3;" : "=l"(d) : "l"(a), "l"(b), "l"(c)); return d;
}
__device__ __forceinline__ float2 up2(uint64_t v) {
    float2 f; asm("mov.b64 {%0, %1}, %2;" : "=f"(f.x), "=f"(f.y) : "l"(v)); return f;
}

// ---------------- GEMM1: gate/value fused + SwiGLU ----------------
// tile: 64(m) x 128(n), BK=16, 256 threads, per-thread 4m x 8n (4 f32x2), two accumulators
__global__ __launch_bounds__(256) void k_gemm1(const float* __restrict__ x,
                                               const float* __restrict__ w1,
                                               const float* __restrict__ w2) {
    const int e   = blockIdx.z;
    const int cnt = g_cnt[e];
    const int m0  = blockIdx.y * 64;
    if (m0 >= cnt) return;
    const int n0  = blockIdx.x * 128;

    __shared__ float As[16][64];
    __shared__ float Bs1[16][128];
    __shared__ float Bs2[16][128];
    __shared__ int   toks[64];

    const int tid = threadIdx.x;
    if (tid < 64) toks[tid] = g_tok[e * CAP + m0 + tid];
    __syncthreads();

    const int am = tid & 63;
    const int ak = (tid >> 6) << 2;          // 0,4,8,12
    const float* aptr = x + (size_t)toks[am] * DM + ak;

    const int bn = (tid & 15) * 8;
    const int bk = tid >> 4;                 // 0..15
    const float* b1p = w1 + (size_t)e * DM * DF + (size_t)bk * DF + n0 + bn;
    const float* b2p = w2 + (size_t)e * DM * DF + (size_t)bk * DF + n0 + bn;

    const int tx = tid & 15, ty = tid >> 4;

    uint64_t acc1[4][4], acc2[4][4];
#pragma unroll
    for (int i = 0; i < 4; i++)
#pragma unroll
        for (int j = 0; j < 4; j++) { acc1[i][j] = 0ull; acc2[i][j] = 0ull; }

    for (int k0 = 0; k0 < DM; k0 += 16) {
        float4 av  = *(const float4*)(aptr + k0);
        float4 b1a = *(const float4*)(b1p);
        float4 b1b = *(const float4*)(b1p + 4);
        float4 b2a = *(const float4*)(b2p);
        float4 b2b = *(const float4*)(b2p + 4);
        b1p += (size_t)16 * DF;
        b2p += (size_t)16 * DF;

        __syncthreads();
        As[ak + 0][am] = av.x; As[ak + 1][am] = av.y;
        As[ak + 2][am] = av.z; As[ak + 3][am] = av.w;
        *(float4*)&Bs1[bk][bn]     = b1a;
        *(float4*)&Bs1[bk][bn + 4] = b1b;
        *(float4*)&Bs2[bk][bn]     = b2a;
        *(float4*)&Bs2[bk][bn + 4] = b2b;
        __syncthreads();

#pragma unroll
        for (int kk = 0; kk < 16; kk++) {
            float4 a = *(const float4*)&As[kk][ty * 4];
            uint64_t aa[4] = {pack2(a.x), pack2(a.y), pack2(a.z), pack2(a.w)};
            const uint64_t* b1 = (const uint64_t*)&Bs1[kk][tx * 8];
            const uint64_t* b2 = (const uint64_t*)&Bs2[kk][tx * 8];
#pragma unroll
            for (int j = 0; j < 4; j++) {
                uint64_t b1v = b1[j], b2v = b2[j];
#pragma unroll
                for (int i = 0; i < 4; i++) {
                    acc1[i][j] = fma2(aa[i], b1v, acc1[i][j]);
                    acc2[i][j] = fma2(aa[i], b2v, acc2[i][j]);
                }
            }
        }
    }

    // epilogue: hidden = silu(gate) * value
#pragma unroll
    for (int i = 0; i < 4; i++) {
        float* hrow = g_hidden + (size_t)(e * CAP + m0 + ty * 4 + i) * DF + n0 + tx * 8;
#pragma unroll
        for (int j = 0; j < 4; j++) {
            float2 g = up2(acc1[i][j]);
            float2 v = up2(acc2[i][j]);
            float2 h;
            h.x = g.x / (1.0f + expf(-g.x)) * v.x;
            h.y = g.y / (1.0f + expf(-g.y)) * v.y;
            *(float2*)(hrow + j * 2) = h;
        }
    }
}

// ---------------- GEMM2: hidden @ w3, weighted scatter-add ----------------
__global__ __launch_bounds__(256) void k_gemm2(const float* __restrict__ w3,
                                               float* __restrict__ out) {
    const int e   = blockIdx.z;
    const int cnt = g_cnt[e];
    const int m0  = blockIdx.y * 64;
    if (m0 >= cnt) return;
    const int n0  = blockIdx.x * 128;

    __shared__ float As[16][64];
    __shared__ float Bs[16][128];
    __shared__ int   toks[64];
    __shared__ float wts[64];

    const int tid = threadIdx.x;
    if (tid < 64) {
        toks[tid] = g_tok[e * CAP + m0 + tid];
        wts[tid]  = g_wt[e * CAP + m0 + tid];
    }

    const int am = tid & 63;
    const int ak = (tid >> 6) << 2;
    const float* aptr = g_hidden + (size_t)(e * CAP + m0 + am) * DF + ak;

    const int bn = (tid & 15) * 8;
    const int bk = tid >> 4;
    const float* bp = w3 + (size_t)e * DF * DM + (size_t)bk * DM + n0 + bn;

    const int tx = tid & 15, ty = tid >> 4;

    uint64_t acc[4][4];
#pragma unroll
    for (int i = 0; i < 4; i++)
#pragma unroll
        for (int j = 0; j < 4; j++) acc[i][j] = 0ull;

    for (int k0 = 0; k0 < DF; k0 += 16) {
        float4 av = *(const float4*)(aptr + k0);
        float4 ba = *(const float4*)(bp);
        float4 bb = *(const float4*)(bp + 4);
        bp += (size_t)16 * DM;

        __syncthreads();
        As[ak + 0][am] = av.x; As[ak + 1][am] = av.y;
        As[ak + 2][am] = av.z; As[ak + 3][am] = av.w;
        *(float4*)&Bs[bk][bn]     = ba;
        *(float4*)&Bs[bk][bn + 4] = bb;
        __syncthreads();

#pragma unroll
        for (int kk = 0; kk < 16; kk++) {
            float4 a = *(const float4*)&As[kk][ty * 4];
            uint64_t aa[4] = {pack2(a.x), pack2(a.y), pack2(a.z), pack2(a.w)};
            const uint64_t* b = (const uint64_t*)&Bs[kk][tx * 8];
#pragma unroll
            for (int j = 0; j < 4; j++) {
                uint64_t bv = b[j];
#pragma unroll
                for (int i = 0; i < 4; i++)
                    acc[i][j] = fma2(aa[i], bv, acc[i][j]);
            }
        }
    }

    // epilogue: out[token] += weight * val   (exactly 2 adds/element -> deterministic)
#pragma unroll
    for (int i = 0; i < 4; i++) {
        int r = ty * 4 + i;
        if (m0 + r < cnt) {
            int   t   = toks[r];
            float wgt = wts[r];
            float* orow = out + (size_t)t * DM + n0 + tx * 8;
#pragma unroll
            for (int j = 0; j < 4; j++) {
                float2 v = up2(acc[i][j]);
                atomicAdd(orow + j * 2,     wgt * v.x);
                atomicAdd(orow + j * 2 + 1, wgt * v.y);
            }
        }
    }
}

// ---------------- launch ----------------
extern "C" void kernel_launch(void* const* d_in, const int* in_sizes, int n_in,
                              void* d_out, int out_size) {
    const float* x   = (const float*)d_in[0];
    const int*   idx = (const int*)  d_in[1];
    const float* ew  = (const float*)d_in[2];
    const float* w1  = (const float*)d_in[3];
    const float* w2  = (const float*)d_in[4];
    const float* w3  = (const float*)d_in[5];
    float* out = (float*)d_out;

    cudaMemsetAsync(out, 0, (size_t)NT * DM * sizeof(float));
    k_zero<<<1, 32>>>();
    k_dispatch<<<(NT * TK + 255) / 256, 256>>>(idx, ew);

    dim3 g1(DF / 128, CAP / 64, NE);
    k_gemm1<<<g1, 256>>>(x, w1, w2);

    dim3 g2(DM / 128, CAP / 64, NE);
    k_gemm2<<<g2, 256>>>(w3, out);
}

// round 2
// speedup vs baseline: 2.0315x; 2.0315x over previous
#include <cuda_runtime.h>
#include <stdint.h>

#define NT 8192
#define TK 2
#define NE 8
#define DM 1024
#define DF 2048
#define CAP 3072

// ---- persistent scratch (device globals; no runtime allocation allowed) ----
__device__ int   g_cnt[NE];
__device__ int   g_tok[NE * CAP];          // zero-init -> always a valid token id
__device__ float g_wt[NE * CAP];
__device__ float g_hidden[(size_t)NE * CAP * DF];   // 201 MB

// ---------------- dispatch ----------------
__global__ void k_zero() { if (threadIdx.x < NE) g_cnt[threadIdx.x] = 0; }

__global__ void k_dispatch(const int* __restrict__ idx, const float* __restrict__ w) {
    int i = blockIdx.x * blockDim.x + threadIdx.x;
    if (i >= NT * TK) return;
    int e = idx[i];
    int p = atomicAdd(&g_cnt[e], 1);
    if (p < CAP) {
        g_tok[e * CAP + p] = i >> 1;
        g_wt[e * CAP + p]  = w[i];
    }
}

// ---------------- packed f32x2 helpers ----------------
__device__ __forceinline__ uint64_t pack2(float v) {
    uint64_t r; asm("mov.b64 %0, {%1, %1};" : "=l"(r) : "f"(v)); return r;
}
__device__ __forceinline__ uint64_t fma2(uint64_t a, uint64_t b, uint64_t c) {
    uint64_t d; asm("fma.rn.f32x2 %0, %1, %2, %3;" : "=l"(d) : "l"(a), "l"(b), "l"(c)); return d;
}
__device__ __forceinline__ float2 up2(uint64_t v) {
    float2 f; asm("mov.b64 {%0, %1}, %2;" : "=f"(f.x), "=f"(f.y) : "l"(v)); return f;
}
__device__ __forceinline__ void red2(float* p, float a, float b) {
    asm volatile("red.global.add.v2.f32 [%0], {%1, %2};" :: "l"(p), "f"(a), "f"(b) : "memory");
}

// ---------------- GEMM1: fused gate/value + SwiGLU ----------------
// tile 128m x (64n per matrix), BK=16, 256 threads, micro 8m x 4n x 2mat
__global__ __launch_bounds__(256, 2) void k_gemm1(const float* __restrict__ x,
                                                  const float* __restrict__ w1,
                                                  const float* __restrict__ w2) {
    const int e   = blockIdx.z;
    const int cnt = g_cnt[e];
    const int m0  = blockIdx.y * 128;
    if (m0 >= cnt) return;
    const int n0  = blockIdx.x * 64;

    __shared__ float As[2][16][132];
    __shared__ float B1s[2][16][64];
    __shared__ float B2s[2][16][64];
    __shared__ int   toks[128];

    const int tid = threadIdx.x;
    if (tid < 128) toks[tid] = g_tok[e * CAP + m0 + tid];
    __syncthreads();

    const int ar  = tid >> 2;            // 0..63
    const int akq = (tid & 3) * 4;       // k offset (floats)
    const float* ap0 = x + (size_t)toks[ar]      * DM + akq;
    const float* ap1 = x + (size_t)toks[ar + 64] * DM + akq;

    const int bkr = tid >> 4;            // 0..15
    const int bnc = (tid & 15) * 4;
    const float* b1p = w1 + (size_t)e * DM * DF + (size_t)bkr * DF + n0 + bnc;
    const float* b2p = w2 + (size_t)e * DM * DF + (size_t)bkr * DF + n0 + bnc;

    const int tx = tid & 15, ty = tid >> 4;

    uint64_t acc1[8][2], acc2[8][2];
#pragma unroll
    for (int i = 0; i < 8; i++) { acc1[i][0] = acc1[i][1] = 0ull; acc2[i][0] = acc2[i][1] = 0ull; }

    float4 ra0 = *(const float4*)(ap0);
    float4 ra1 = *(const float4*)(ap1);
    float4 rb1 = *(const float4*)(b1p);
    float4 rb2 = *(const float4*)(b2p);

    int buf = 0;
    for (int t = 0; t < DM / 16; t++) {
        As[buf][akq + 0][ar] = ra0.x; As[buf][akq + 1][ar] = ra0.y;
        As[buf][akq + 2][ar] = ra0.z; As[buf][akq + 3][ar] = ra0.w;
        As[buf][akq + 0][ar + 64] = ra1.x; As[buf][akq + 1][ar + 64] = ra1.y;
        As[buf][akq + 2][ar + 64] = ra1.z; As[buf][akq + 3][ar + 64] = ra1.w;
        *(float4*)&B1s[buf][bkr][bnc] = rb1;
        *(float4*)&B2s[buf][bkr][bnc] = rb2;
        __syncthreads();

        if (t + 1 < DM / 16) {
            int k0 = (t + 1) * 16;
            ra0 = *(const float4*)(ap0 + k0);
            ra1 = *(const float4*)(ap1 + k0);
            rb1 = *(const float4*)(b1p + (size_t)k0 * DF);
            rb2 = *(const float4*)(b2p + (size_t)k0 * DF);
        }

#pragma unroll
        for (int kk = 0; kk < 16; kk++) {
            float4 a0 = *(const float4*)&As[buf][kk][ty * 8];
            float4 a1 = *(const float4*)&As[buf][kk][ty * 8 + 4];
            uint64_t aa[8] = {pack2(a0.x), pack2(a0.y), pack2(a0.z), pack2(a0.w),
                              pack2(a1.x), pack2(a1.y), pack2(a1.z), pack2(a1.w)};
            const uint64_t* b1 = (const uint64_t*)&B1s[buf][kk][tx * 4];
            const uint64_t* b2 = (const uint64_t*)&B2s[buf][kk][tx * 4];
            uint64_t b10 = b1[0], b11 = b1[1], b20 = b2[0], b21 = b2[1];
#pragma unroll
            for (int i = 0; i < 8; i++) {
                acc1[i][0] = fma2(aa[i], b10, acc1[i][0]);
                acc1[i][1] = fma2(aa[i], b11, acc1[i][1]);
                acc2[i][0] = fma2(aa[i], b20, acc2[i][0]);
                acc2[i][1] = fma2(aa[i], b21, acc2[i][1]);
            }
        }
        buf ^= 1;
    }

    // epilogue: hidden = silu(gate) * value
#pragma unroll
    for (int i = 0; i < 8; i++) {
        float* hrow = g_hidden + (size_t)(e * CAP + m0 + ty * 8 + i) * DF + n0 + tx * 4;
        float2 g0 = up2(acc1[i][0]), g1 = up2(acc1[i][1]);
        float2 v0 = up2(acc2[i][0]), v1 = up2(acc2[i][1]);
        float4 h;
        h.x = g0.x / (1.0f + __expf(-g0.x)) * v0.x;
        h.y = g0.y / (1.0f + __expf(-g0.y)) * v0.y;
        h.z = g1.x / (1.0f + __expf(-g1.x)) * v1.x;
        h.w = g1.y / (1.0f + __expf(-g1.y)) * v1.y;
        *(float4*)hrow = h;
    }
}

// ---------------- GEMM2: hidden @ w3, weighted scatter-add ----------------
// tile 128m x 128n, BK=16, 256 threads, micro 8m x 8n (n split as tx*4 and 64+tx*4)
__global__ __launch_bounds__(256, 2) void k_gemm2(const float* __restrict__ w3,
                                                  float* __restrict__ out) {
    const int e   = blockIdx.z;
    const int cnt = g_cnt[e];
    const int m0  = blockIdx.y * 128;
    if (m0 >= cnt) return;
    const int n0  = blockIdx.x * 128;

    __shared__ float As[2][16][132];
    __shared__ float Bs[2][16][128];
    __shared__ int   toks[128];
    __shared__ float wts[128];

    const int tid = threadIdx.x;
    if (tid < 128) { toks[tid] = g_tok[e * CAP + m0 + tid]; wts[tid] = g_wt[e * CAP + m0 + tid]; }

    const int ar  = tid >> 2;            // 0..63
    const int akq = (tid & 3) * 4;
    const float* ap0 = g_hidden + (size_t)(e * CAP + m0 + ar) * DF + akq;
    const float* ap1 = ap0 + (size_t)64 * DF;

    const int bkr = tid >> 5;            // 0..7 (rows bkr, bkr+8)
    const int bnc = (tid & 31) * 4;
    const float* bp = w3 + (size_t)e * DF * DM + (size_t)bkr * DM + n0 + bnc;

    const int tx = tid & 15, ty = tid >> 4;

    uint64_t acc[8][4];
#pragma unroll
    for (int i = 0; i < 8; i++) { acc[i][0] = acc[i][1] = acc[i][2] = acc[i][3] = 0ull; }

    float4 ra0 = *(const float4*)(ap0);
    float4 ra1 = *(const float4*)(ap1);
    float4 rb0 = *(const float4*)(bp);
    float4 rb1 = *(const float4*)(bp + (size_t)8 * DM);

    int buf = 0;
    for (int t = 0; t < DF / 16; t++) {
        As[buf][akq + 0][ar] = ra0.x; As[buf][akq + 1][ar] = ra0.y;
        As[buf][akq + 2][ar] = ra0.z; As[buf][akq + 3][ar] = ra0.w;
        As[buf][akq + 0][ar + 64] = ra1.x; As[buf][akq + 1][ar + 64] = ra1.y;
        As[buf][akq + 2][ar + 64] = ra1.z; As[buf][akq + 3][ar + 64] = ra1.w;
        *(float4*)&Bs[buf][bkr][bnc]     = rb0;
        *(float4*)&Bs[buf][bkr + 8][bnc] = rb1;
        __syncthreads();

        if (t + 1 < DF / 16) {
            int k0 = (t + 1) * 16;
            ra0 = *(const float4*)(ap0 + k0);
            ra1 = *(const float4*)(ap1 + k0);
            rb0 = *(const float4*)(bp + (size_t)k0 * DM);
            rb1 = *(const float4*)(bp + (size_t)(k0 + 8) * DM);
        }

#pragma unroll
        for (int kk = 0; kk < 16; kk++) {
            float4 a0 = *(const float4*)&As[buf][kk][ty * 8];
            float4 a1 = *(const float4*)&As[buf][kk][ty * 8 + 4];
            uint64_t aa[8] = {pack2(a0.x), pack2(a0.y), pack2(a0.z), pack2(a0.w),
                              pack2(a1.x), pack2(a1.y), pack2(a1.z), pack2(a1.w)};
            const uint64_t* bL = (const uint64_t*)&Bs[buf][kk][tx * 4];
            const uint64_t* bH = (const uint64_t*)&Bs[buf][kk][64 + tx * 4];
            uint64_t b0 = bL[0], b1 = bL[1], b2 = bH[0], b3 = bH[1];
#pragma unroll
            for (int i = 0; i < 8; i++) {
                acc[i][0] = fma2(aa[i], b0, acc[i][0]);
                acc[i][1] = fma2(aa[i], b1, acc[i][1]);
                acc[i][2] = fma2(aa[i], b2, acc[i][2]);
                acc[i][3] = fma2(aa[i], b3, acc[i][3]);
            }
        }
        buf ^= 1;
    }

    // epilogue: out[token] += weight * val   (exactly TOP_K=2 adds/element)
#pragma unroll
    for (int i = 0; i < 8; i++) {
        int r = ty * 8 + i;
        if (m0 + r < cnt) {
            float wgt  = wts[r];
            float* o   = out + (size_t)toks[r] * DM + n0;
            float2 p;
            p = up2(acc[i][0]); red2(o + tx * 4,          wgt * p.x, wgt * p.y);
            p = up2(acc[i][1]); red2(o + tx * 4 + 2,      wgt * p.x, wgt * p.y);
            p = up2(acc[i][2]); red2(o + 64 + tx * 4,     wgt * p.x, wgt * p.y);
            p = up2(acc[i][3]); red2(o + 64 + tx * 4 + 2, wgt * p.x, wgt * p.y);
        }
    }
}

// ---------------- launch ----------------
extern "C" void kernel_launch(void* const* d_in, const int* in_sizes, int n_in,
                              void* d_out, int out_size) {
    const float* x   = (const float*)d_in[0];
    const int*   idx = (const int*)  d_in[1];
    const float* ew  = (const float*)d_in[2];
    const float* w1  = (const float*)d_in[3];
    const float* w2  = (const float*)d_in[4];
    const float* w3  = (const float*)d_in[5];
    float* out = (float*)d_out;

    cudaMemsetAsync(out, 0, (size_t)out_size * sizeof(float));
    k_zero<<<1, 32>>>();
    k_dispatch<<<(NT * TK + 255) / 256, 256>>>(idx, ew);

    dim3 g1(DF / 64, CAP / 128, NE);
    k_gemm1<<<g1, 256>>>(x, w1, w2);

    dim3 g2(DM / 128, CAP / 128, NE);
    k_gemm2<<<g2, 256>>>(w3, out);
}

// round 3
// speedup vs baseline: 2.0345x; 1.0015x over previous
#include <cuda_runtime.h>
#include <stdint.h>

#define NT 8192
#define TK 2
#define NE 8
#define DM 1024
#define DF 2048
#define CAP 3072

// ---- persistent scratch (device globals; no runtime allocation allowed) ----
__device__ int   g_cnt[NE];
__device__ int   g_tok[NE * CAP];          // zero-init -> always a valid token id
__device__ float g_wt[NE * CAP];
__device__ float g_hidden[(size_t)NE * CAP * DF];   // 201 MB

// ---------------- dispatch ----------------
__global__ void k_zero() { if (threadIdx.x < NE) g_cnt[threadIdx.x] = 0; }

__global__ void k_dispatch(const int* __restrict__ idx, const float* __restrict__ w) {
    int i = blockIdx.x * blockDim.x + threadIdx.x;
    if (i >= NT * TK) return;
    int e = idx[i];
    int p = atomicAdd(&g_cnt[e], 1);
    if (p < CAP) {
        g_tok[e * CAP + p] = i >> 1;
        g_wt[e * CAP + p]  = w[i];
    }
}

// ---------------- packed f32x2 helpers ----------------
__device__ __forceinline__ uint64_t pack2(float v) {
    uint64_t r; asm("mov.b64 %0, {%1, %1};" : "=l"(r) : "f"(v)); return r;
}
__device__ __forceinline__ uint64_t fma2(uint64_t a, uint64_t b, uint64_t c) {
    uint64_t d; asm("fma.rn.f32x2 %0, %1, %2, %3;" : "=l"(d) : "l"(a), "l"(b), "l"(c)); return d;
}
__device__ __forceinline__ float2 up2(uint64_t v) {
    float2 f; asm("mov.b64 {%0, %1}, %2;" : "=f"(f.x), "=f"(f.y) : "l"(v)); return f;
}
__device__ __forceinline__ void red2(float* p, float a, float b) {
    asm volatile("red.global.add.v2.f32 [%0], {%1, %2};" :: "l"(p), "f"(a), "f"(b) : "memory");
}

// ---------------- GEMM1: fused gate/value + SwiGLU ----------------
// tile 128m x (64n per matrix), BK=16, 256 threads, micro 8m x 4n x 2mat
__global__ __launch_bounds__(256, 2) void k_gemm1(const float* __restrict__ x,
                                                  const float* __restrict__ w1,
                                                  const float* __restrict__ w2) {
    const int e   = blockIdx.z;
    const int cnt = g_cnt[e];
    const int m0  = blockIdx.y * 128;
    if (m0 >= cnt) return;
    const int n0  = blockIdx.x * 64;

    __shared__ float As[2][16][132];
    __shared__ float B1s[2][16][64];
    __shared__ float B2s[2][16][64];
    __shared__ int   toks[128];

    const int tid = threadIdx.x;
    if (tid < 128) toks[tid] = g_tok[e * CAP + m0 + tid];
    __syncthreads();

    const int ar  = tid >> 2;            // 0..63
    const int akq = (tid & 3) * 4;       // k offset (floats)
    const float* ap0 = x + (size_t)toks[ar]      * DM + akq;
    const float* ap1 = x + (size_t)toks[ar + 64] * DM + akq;

    const int bkr = tid >> 4;            // 0..15
    const int bnc = (tid & 15) * 4;
    const float* b1p = w1 + (size_t)e * DM * DF + (size_t)bkr * DF + n0 + bnc;
    const float* b2p = w2 + (size_t)e * DM * DF + (size_t)bkr * DF + n0 + bnc;

    const int tx = tid & 15, ty = tid >> 4;

    uint64_t acc1[8][2], acc2[8][2];
#pragma unroll
    for (int i = 0; i < 8; i++) { acc1[i][0] = acc1[i][1] = 0ull; acc2[i][0] = acc2[i][1] = 0ull; }

    float4 ra0 = *(const float4*)(ap0);
    float4 ra1 = *(const float4*)(ap1);
    float4 rb1 = *(const float4*)(b1p);
    float4 rb2 = *(const float4*)(b2p);

    int buf = 0;
    for (int t = 0; t < DM / 16; t++) {
        As[buf][akq + 0][ar] = ra0.x; As[buf][akq + 1][ar] = ra0.y;
        As[buf][akq + 2][ar] = ra0.z; As[buf][akq + 3][ar] = ra0.w;
        As[buf][akq + 0][ar + 64] = ra1.x; As[buf][akq + 1][ar + 64] = ra1.y;
        As[buf][akq + 2][ar + 64] = ra1.z; As[buf][akq + 3][ar + 64] = ra1.w;
        *(float4*)&B1s[buf][bkr][bnc] = rb1;
        *(float4*)&B2s[buf][bkr][bnc] = rb2;
        __syncthreads();

        if (t + 1 < DM / 16) {
            int k0 = (t + 1) * 16;
            ra0 = *(const float4*)(ap0 + k0);
            ra1 = *(const float4*)(ap1 + k0);
            rb1 = *(const float4*)(b1p + (size_t)k0 * DF);
            rb2 = *(const float4*)(b2p + (size_t)k0 * DF);
        }

#pragma unroll
        for (int kk = 0; kk < 16; kk++) {
            float4 a0 = *(const float4*)&As[buf][kk][ty * 8];
            float4 a1 = *(const float4*)&As[buf][kk][ty * 8 + 4];
            uint64_t aa[8] = {pack2(a0.x), pack2(a0.y), pack2(a0.z), pack2(a0.w),
                              pack2(a1.x), pack2(a1.y), pack2(a1.z), pack2(a1.w)};
            const uint64_t* b1 = (const uint64_t*)&B1s[buf][kk][tx * 4];
            const uint64_t* b2 = (const uint64_t*)&B2s[buf][kk][tx * 4];
            uint64_t b10 = b1[0], b11 = b1[1], b20 = b2[0], b21 = b2[1];
#pragma unroll
            for (int i = 0; i < 8; i++) {
                acc1[i][0] = fma2(aa[i], b10, acc1[i][0]);
                acc1[i][1] = fma2(aa[i], b11, acc1[i][1]);
                acc2[i][0] = fma2(aa[i], b20, acc2[i][0]);
                acc2[i][1] = fma2(aa[i], b21, acc2[i][1]);
            }
        }
        buf ^= 1;
    }

    // epilogue: hidden = silu(gate) * value
#pragma unroll
    for (int i = 0; i < 8; i++) {
        float* hrow = g_hidden + (size_t)(e * CAP + m0 + ty * 8 + i) * DF + n0 + tx * 4;
        float2 g0 = up2(acc1[i][0]), g1 = up2(acc1[i][1]);
        float2 v0 = up2(acc2[i][0]), v1 = up2(acc2[i][1]);
        float4 h;
        h.x = g0.x / (1.0f + __expf(-g0.x)) * v0.x;
        h.y = g0.y / (1.0f + __expf(-g0.y)) * v0.y;
        h.z = g1.x / (1.0f + __expf(-g1.x)) * v1.x;
        h.w = g1.y / (1.0f + __expf(-g1.y)) * v1.y;
        *(float4*)hrow = h;
    }
}

// ---------------- GEMM2: hidden @ w3, weighted scatter-add ----------------
// tile 128m x 128n, BK=16, 256 threads, micro 8m x 8n (n split as tx*4 and 64+tx*4)
__global__ __launch_bounds__(256, 2) void k_gemm2(const float* __restrict__ w3,
                                                  float* __restrict__ out) {
    const int e   = blockIdx.z;
    const int cnt = g_cnt[e];
    const int m0  = blockIdx.y * 128;
    if (m0 >= cnt) return;
    const int n0  = blockIdx.x * 128;

    __shared__ float As[2][16][132];
    __shared__ float Bs[2][16][128];
    __shared__ int   toks[128];
    __shared__ float wts[128];

    const int tid = threadIdx.x;
    if (tid < 128) { toks[tid] = g_tok[e * CAP + m0 + tid]; wts[tid] = g_wt[e * CAP + m0 + tid]; }

    const int ar  = tid >> 2;            // 0..63
    const int akq = (tid & 3) * 4;
    const float* ap0 = g_hidden + (size_t)(e * CAP + m0 + ar) * DF + akq;
    const float* ap1 = ap0 + (size_t)64 * DF;

    const int bkr = tid >> 5;            // 0..7 (rows bkr, bkr+8)
    const int bnc = (tid & 31) * 4;
    const float* bp = w3 + (size_t)e * DF * DM + (size_t)bkr * DM + n0 + bnc;

    const int tx = tid & 15, ty = tid >> 4;

    uint64_t acc[8][4];
#pragma unroll
    for (int i = 0; i < 8; i++) { acc[i][0] = acc[i][1] = acc[i][2] = acc[i][3] = 0ull; }

    float4 ra0 = *(const float4*)(ap0);
    float4 ra1 = *(const float4*)(ap1);
    float4 rb0 = *(const float4*)(bp);
    float4 rb1 = *(const float4*)(bp + (size_t)8 * DM);

    int buf = 0;
    for (int t = 0; t < DF / 16; t++) {
        As[buf][akq + 0][ar] = ra0.x; As[buf][akq + 1][ar] = ra0.y;
        As[buf][akq + 2][ar] = ra0.z; As[buf][akq + 3][ar] = ra0.w;
        As[buf][akq + 0][ar + 64] = ra1.x; As[buf][akq + 1][ar + 64] = ra1.y;
        As[buf][akq + 2][ar + 64] = ra1.z; As[buf][akq + 3][ar + 64] = ra1.w;
        *(float4*)&Bs[buf][bkr][bnc]     = rb0;
        *(float4*)&Bs[buf][bkr + 8][bnc] = rb1;
        __syncthreads();

        if (t + 1 < DF / 16) {
            int k0 = (t + 1) * 16;
            ra0 = *(const float4*)(ap0 + k0);
            ra1 = *(const float4*)(ap1 + k0);
            rb0 = *(const float4*)(bp + (size_t)k0 * DM);
            rb1 = *(const float4*)(bp + (size_t)(k0 + 8) * DM);
        }

#pragma unroll
        for (int kk = 0; kk < 16; kk++) {
            float4 a0 = *(const float4*)&As[buf][kk][ty * 8];
            float4 a1 = *(const float4*)&As[buf][kk][ty * 8 + 4];
            uint64_t aa[8] = {pack2(a0.x), pack2(a0.y), pack2(a0.z), pack2(a0.w),
                              pack2(a1.x), pack2(a1.y), pack2(a1.z), pack2(a1.w)};
            const uint64_t* bL = (const uint64_t*)&Bs[buf][kk][tx * 4];
            const uint64_t* bH = (const uint64_t*)&Bs[buf][kk][64 + tx * 4];
            uint64_t b0 = bL[0], b1 = bL[1], b2 = bH[0], b3 = bH[1];
#pragma unroll
            for (int i = 0; i < 8; i++) {
                acc[i][0] = fma2(aa[i], b0, acc[i][0]);
                acc[i][1] = fma2(aa[i], b1, acc[i][1]);
                acc[i][2] = fma2(aa[i], b2, acc[i][2]);
                acc[i][3] = fma2(aa[i], b3, acc[i][3]);
            }
        }
        buf ^= 1;
    }

    // epilogue: out[token] += weight * val   (exactly TOP_K=2 adds/element)
#pragma unroll
    for (int i = 0; i < 8; i++) {
        int r = ty * 8 + i;
        if (m0 + r < cnt) {
            float wgt  = wts[r];
            float* o   = out + (size_t)toks[r] * DM + n0;
            float2 p;
            p = up2(acc[i][0]); red2(o + tx * 4,          wgt * p.x, wgt * p.y);
            p = up2(acc[i][1]); red2(o + tx * 4 + 2,      wgt * p.x, wgt * p.y);
            p = up2(acc[i][2]); red2(o + 64 + tx * 4,     wgt * p.x, wgt * p.y);
            p = up2(acc[i][3]); red2(o + 64 + tx * 4 + 2, wgt * p.x, wgt * p.y);
        }
    }
}

// ---------------- launch ----------------
extern "C" void kernel_launch(void* const* d_in, const int* in_sizes, int n_in,
                              void* d_out, int out_size) {
    const float* x   = (const float*)d_in[0];
    const int*   idx = (const int*)  d_in[1];
    const float* ew  = (const float*)d_in[2];
    const float* w1  = (const float*)d_in[3];
    const float* w2  = (const float*)d_in[4];
    const float* w3  = (const float*)d_in[5];
    float* out = (float*)d_out;

    cudaMemsetAsync(out, 0, (size_t)out_size * sizeof(float));
    k_zero<<<1, 32>>>();
    k_dispatch<<<(NT * TK + 255) / 256, 256>>>(idx, ew);

    dim3 g1(DF / 64, CAP / 128, NE);
    k_gemm1<<<g1, 256>>>(x, w1, w2);

    dim3 g2(DM / 128, CAP / 128, NE);
    k_gemm2<<<g2, 256>>>(w3, out);
}